// round 9
// baseline (speedup 1.0000x reference)
#include <cuda_runtime.h>
#include <cstdint>
#include <cstddef>
#include <math.h>

// =====================================================================
// AutoCompleteDecoderModel as ONE persistent kernel (single graph node).
// 128 blocks x 256 threads, all co-resident (<=148 SMs) -> safe software
// grid barrier. Phases per step are separated by gridbar():
//   encoder t: [gates GEMM split-K2] bar [LSTM cell] bar
//   decoder t: [gates GEMM] bar [cell] bar [q GEMM] bar
//              [attention per-row, online softmax] bar
//              [Vnew GEMM] bar [combine+tanh+logits+CE per-row] bar
// Final loss reduction by block 0.
// B=128, Lc=Le=512, H=512, V=128.
// =====================================================================

#define BB 128
#define HH 512
#define VV 128
#define LC 512
#define LE 512
#define NB 128
#define NT 256

struct Seg { const float* A; long lda; const float* W; long ldw; int K; };

// ---------------- device scratch (allocation-free rule) ----------------
__device__ float g_h[BB * HH];
__device__ float g_c[BB * HH];
__device__ float g_Vp[BB * HH];
__device__ float g_attn[BB * HH];
__device__ float g_gates[2 * (size_t)BB * 2048];
__device__ float g_qp[8 * (size_t)BB * HH];
__device__ float g_vpart[8 * (size_t)BB * HH];
__device__ float g_hs[(size_t)BB * LC * HH];     // encoder hiddens, 134MB
__device__ float g_nll[(LE - 1) * BB];
__device__ unsigned g_count;                     // grid barrier state
__device__ volatile unsigned g_gen;

__device__ __forceinline__ float sigf(float x) { return 1.f / (1.f + expf(-x)); }

// ---------------- software grid barrier (all NB blocks resident) --------
// Arrive: one L2 atomic per block. Wait: plain volatile L2 load (no RMW
// serialization). Release: last block bumps generation after threadfence.
__device__ __forceinline__ void gridbar() {
    __syncthreads();
    if (threadIdx.x == 0) {
        __threadfence();
        unsigned g = g_gen;
        if (atomicAdd(&g_count, 1u) == NB - 1) {
            g_count = 0u;
            __threadfence();
            g_gen = g + 1u;
        } else {
            while (g_gen == g) __nanosleep(32);
        }
        __threadfence();
    }
    __syncthreads();
}

// ---------------- one GEMM tile job: out = A @ W^T over [kstart,kend) ----
// 64x64 tile at (rowBase, colBase), K segments s0|s1|s2, 16-wide k steps.
// Segment boundaries must be multiples of 16.
__device__ __forceinline__ void gemm_job(
    float (*As)[68], float (*Bs)[68],
    const Seg& s0, const Seg& s1, const Seg& s2,
    int N, int rowBase, int colBase, int kstart, int kend,
    float* __restrict__ out)
{
    const int tid = threadIdx.x;
    const int tx = tid & 15, ty = tid >> 4;
    const int lm = tid >> 2;          // 0..63: row within tile for loads
    const int lkq = (tid & 3) * 4;    // k quad within 16

    float acc[4][4];
#pragma unroll
    for (int i = 0; i < 4; i++)
#pragma unroll
        for (int j = 0; j < 4; j++) acc[i][j] = 0.f;

    for (int kg = kstart; kg < kend; kg += 16) {
        const float *A, *W; long lda, ldw; int lk = kg;
        if (lk < s0.K)      { A = s0.A; W = s0.W; lda = s0.lda; ldw = s0.ldw; }
        else {
            lk -= s0.K;
            if (lk < s1.K)  { A = s1.A; W = s1.W; lda = s1.lda; ldw = s1.ldw; }
            else { lk -= s1.K; A = s2.A; W = s2.W; lda = s2.lda; ldw = s2.ldw; }
        }
        float4 va = *reinterpret_cast<const float4*>(A + (size_t)(rowBase + lm) * lda + lk + lkq);
        float4 vb = *reinterpret_cast<const float4*>(W + (size_t)(colBase + lm) * ldw + lk + lkq);
        As[lkq + 0][lm] = va.x; As[lkq + 1][lm] = va.y;
        As[lkq + 2][lm] = va.z; As[lkq + 3][lm] = va.w;
        Bs[lkq + 0][lm] = vb.x; Bs[lkq + 1][lm] = vb.y;
        Bs[lkq + 2][lm] = vb.z; Bs[lkq + 3][lm] = vb.w;
        __syncthreads();
#pragma unroll
        for (int k = 0; k < 16; k++) {
            float4 a4 = *reinterpret_cast<const float4*>(&As[k][ty * 4]);
            float4 b4 = *reinterpret_cast<const float4*>(&Bs[k][tx * 4]);
            float av[4] = {a4.x, a4.y, a4.z, a4.w};
            float bv[4] = {b4.x, b4.y, b4.z, b4.w};
#pragma unroll
            for (int i = 0; i < 4; i++)
#pragma unroll
                for (int j = 0; j < 4; j++) acc[i][j] += av[i] * bv[j];
        }
        __syncthreads();
    }
#pragma unroll
    for (int i = 0; i < 4; i++) {
        float4 v = make_float4(acc[i][0], acc[i][1], acc[i][2], acc[i][3]);
        *reinterpret_cast<float4*>(out + (size_t)(rowBase + ty * 4 + i) * N + colBase + tx * 4) = v;
    }
}

// =====================================================================
__global__ __launch_bounds__(NT) void model_kernel(
    const float* __restrict__ C, const int* __restrict__ C_pad,
    const int* __restrict__ E, const float* __restrict__ E_emb,
    const float* __restrict__ enc_Wih, const float* __restrict__ enc_Whh,
    const float* __restrict__ enc_bih, const float* __restrict__ enc_bhh,
    const float* __restrict__ dec_Wih, const float* __restrict__ dec_Whh,
    const float* __restrict__ dec_bih, const float* __restrict__ dec_bhh,
    const float* __restrict__ att_W, const float* __restrict__ out_W,
    const float* __restrict__ out_b, const float* __restrict__ voc_W,
    const float* __restrict__ voc_b, float* __restrict__ out)
{
    __shared__ __align__(16) float As[16][68];
    __shared__ __align__(16) float Bs[16][68];
    __shared__ __align__(16) float qs[HH];
    __shared__ __align__(16) float wacc[8][HH];
    __shared__ float wm[8], ws[8];
    __shared__ __align__(16) float tv_sm[HH];
    __shared__ float lg_sm[128];
    __shared__ float red[NT];
    __shared__ float red2[NT];

    const int blk = blockIdx.x, tid = threadIdx.x;
    float* h = g_h; float* c = g_c; float* Vp = g_Vp;
    float* attn = g_attn; float* gates = g_gates;
    float* qp = g_qp; float* vpart = g_vpart;
    float* hs = g_hs; float* nll = g_nll;

    const Seg zseg{nullptr, 0, nullptr, 0, 0};

    // ---- zero init recurrent state (every replay) ----
    for (int i = blk * NT + tid; i < BB * HH; i += NB * NT) {
        h[i] = 0.f; c[i] = 0.f; Vp[i] = 0.f;
    }
    gridbar();

    // gates GEMM job decode (N=2048): 2 row tiles x 32 col tiles x 2 K-splits
    const int gcol = (blk & 31) * 64;
    const int grow = ((blk >> 5) & 1) * 64;
    const int gz   = blk >> 6;
    // small GEMM job decode (N=512): 2 row tiles x 8 col tiles x 8 K-splits
    const int scol = (blk & 7) * 64;
    const int srow = ((blk >> 3) & 1) * 64;
    const int sz   = blk >> 4;

    // ================= encoder: 512 steps =================
    for (int t = 0; t < LC; t++) {
        Seg s0{C + (size_t)t * VV, (long)LC * VV, enc_Wih, VV, VV};   // x_t @ Wih^T
        Seg s1{h, HH, enc_Whh, HH, HH};                               // h @ Whh^T
        gemm_job(As, Bs, s0, s1, zseg, 2048, grow, gcol,
                 gz * 320, gz * 320 + 320, gates + (size_t)gz * BB * 2048);
        gridbar();
        for (int idx = blk * NT + tid; idx < BB * HH; idx += NB * NT) {
            int b = idx >> 9, j = idx & 511;
            float gi = enc_bih[j] + enc_bhh[j];
            float gf = enc_bih[512 + j] + enc_bhh[512 + j];
            float gg = enc_bih[1024 + j] + enc_bhh[1024 + j];
            float go = enc_bih[1536 + j] + enc_bhh[1536 + j];
#pragma unroll
            for (int z = 0; z < 2; z++) {
                const float* g = gates + (size_t)z * BB * 2048 + (size_t)b * 2048;
                gi += g[j]; gf += g[512 + j]; gg += g[1024 + j]; go += g[1536 + j];
            }
            float cn = sigf(gf) * c[idx] + sigf(gi) * tanhf(gg);
            float hn = sigf(go) * tanhf(cn);
            c[idx] = cn;
            h[idx] = hn;
            hs[(size_t)b * (LC * HH) + (size_t)t * HH + j] = hn;
        }
        gridbar();
    }

    // ================= decoder: 511 steps =================
    for (int t = 0; t < LE - 1; t++) {
        // ---- gates GEMM: [e_t | Vprev] @ Wih^T + h @ Whh^T, K=1152, split2
        Seg s0{E_emb + (size_t)t * VV, (long)LE * VV, dec_Wih, (long)(VV + HH), VV};
        Seg s1{Vp, HH, dec_Wih + VV, (long)(VV + HH), HH};
        Seg s2{h, HH, dec_Whh, HH, HH};
        gemm_job(As, Bs, s0, s1, s2, 2048, grow, gcol,
                 gz * 576, gz * 576 + 576, gates + (size_t)gz * BB * 2048);
        gridbar();

        // ---- LSTM cell
        for (int idx = blk * NT + tid; idx < BB * HH; idx += NB * NT) {
            int b = idx >> 9, j = idx & 511;
            float gi = dec_bih[j] + dec_bhh[j];
            float gf = dec_bih[512 + j] + dec_bhh[512 + j];
            float gg = dec_bih[1024 + j] + dec_bhh[1024 + j];
            float go = dec_bih[1536 + j] + dec_bhh[1536 + j];
#pragma unroll
            for (int z = 0; z < 2; z++) {
                const float* g = gates + (size_t)z * BB * 2048 + (size_t)b * 2048;
                gi += g[j]; gf += g[512 + j]; gg += g[1024 + j]; go += g[1536 + j];
            }
            float cn = sigf(gf) * c[idx] + sigf(gi) * tanhf(gg);
            float hn = sigf(go) * tanhf(cn);
            c[idx] = cn;
            h[idx] = hn;
        }
        gridbar();

        // ---- q = h @ attW^T (N=512, K=512, split8)
        {
            Seg sq{h, HH, att_W, HH, HH};
            gemm_job(As, Bs, sq, zseg, zseg, HH, srow, scol,
                     sz * 64, sz * 64 + 64, qp + (size_t)sz * BB * HH);
        }
        gridbar();

        // ---- attention for row b = blk: single pass, online softmax
        {
            const int b = blk;
            for (int jj = tid; jj < HH; jj += NT) {
                float qv = 0.f;
#pragma unroll
                for (int z = 0; z < 8; z++) qv += qp[(size_t)z * (BB * HH) + b * HH + jj];
                qs[jj] = qv;
            }
            __syncthreads();

            const int warp = tid >> 5, lane = tid & 31;
            float4 qreg[4];
#pragma unroll
            for (int cch = 0; cch < 4; cch++)
                qreg[cch] = *reinterpret_cast<const float4*>(&qs[cch * 128 + lane * 4]);

            const float* eb = hs + (size_t)b * (LC * HH);
            const int* pb = C_pad + b * LC;

            float m = -INFINITY, s = 0.f;
            float4 a4[4];
#pragma unroll
            for (int cch = 0; cch < 4; cch++) a4[cch] = make_float4(0.f, 0.f, 0.f, 0.f);

            for (int l = warp; l < LC; l += 8) {
                if (pb[l]) continue;                 // masked (warp-uniform)
                const float4* e4 = reinterpret_cast<const float4*>(eb + (size_t)l * HH);
                float4 ev[4];
#pragma unroll
                for (int cch = 0; cch < 4; cch++) ev[cch] = e4[cch * 32 + lane];
                float p = 0.f;
#pragma unroll
                for (int cch = 0; cch < 4; cch++)
                    p += ev[cch].x * qreg[cch].x + ev[cch].y * qreg[cch].y +
                         ev[cch].z * qreg[cch].z + ev[cch].w * qreg[cch].w;
#pragma unroll
                for (int off = 16; off; off >>= 1) p += __shfl_xor_sync(0xffffffffu, p, off);
                float mn = fmaxf(m, p);
                float sc = __expf(m - mn);           // 0 on first valid l
                float wl = __expf(p - mn);
                s = s * sc + wl;
#pragma unroll
                for (int cch = 0; cch < 4; cch++) {
                    a4[cch].x = a4[cch].x * sc + wl * ev[cch].x;
                    a4[cch].y = a4[cch].y * sc + wl * ev[cch].y;
                    a4[cch].z = a4[cch].z * sc + wl * ev[cch].z;
                    a4[cch].w = a4[cch].w * sc + wl * ev[cch].w;
                }
                m = mn;
            }
            if (lane == 0) { wm[warp] = m; ws[warp] = s; }
#pragma unroll
            for (int cch = 0; cch < 4; cch++)
                *reinterpret_cast<float4*>(&wacc[warp][cch * 128 + lane * 4]) = a4[cch];
            __syncthreads();

            float M = -INFINITY;
#pragma unroll
            for (int w = 0; w < 8; w++) M = fmaxf(M, wm[w]);
            float S = 0.f, scw[8];
#pragma unroll
            for (int w = 0; w < 8; w++) {
                scw[w] = (ws[w] > 0.f) ? __expf(wm[w] - M) : 0.f;
                S += ws[w] * scw[w];
            }
            for (int hidx = tid; hidx < HH; hidx += NT) {
                float a = 0.f;
#pragma unroll
                for (int w = 0; w < 8; w++) a += scw[w] * wacc[w][hidx];
                attn[b * HH + hidx] = a / S;
            }
        }
        gridbar();

        // ---- Vnew = [h | attn] @ outW^T (N=512, K=1024, split8)
        {
            Seg sv0{h, HH, out_W, (long)(2 * HH), HH};
            Seg sv1{attn, HH, out_W + HH, (long)(2 * HH), HH};
            gemm_job(As, Bs, sv0, sv1, zseg, HH, srow, scol,
                     sz * 128, sz * 128 + 128, vpart + (size_t)sz * BB * HH);
        }
        gridbar();

        // ---- combine + bias + tanh + logits + CE for row b = blk
        {
            const int b = blk;
            for (int j = tid; j < HH; j += NT) {
                float v = out_b[j];
#pragma unroll
                for (int z = 0; z < 8; z++) v += vpart[(size_t)z * (BB * HH) + b * HH + j];
                Vp[b * HH + j] = v;                 // raw Vnew feeds next step
                tv_sm[j] = tanhf(v);
            }
            __syncthreads();

            float logit = 0.f;
            if (tid < 128) {
                const float4* w4 = reinterpret_cast<const float4*>(voc_W + (size_t)tid * HH);
                float a = 0.f;
#pragma unroll 4
                for (int k = 0; k < 128; k++) {
                    float4 w = w4[k];
                    a += w.x * tv_sm[4 * k] + w.y * tv_sm[4 * k + 1] +
                         w.z * tv_sm[4 * k + 2] + w.w * tv_sm[4 * k + 3];
                }
                logit = a + voc_b[tid];
                lg_sm[tid] = logit;
            }
            red[tid] = (tid < 128) ? logit : -INFINITY;
            __syncthreads();
            for (int o = 128; o; o >>= 1) {
                if (tid < o) red[tid] = fmaxf(red[tid], red[tid + o]);
                __syncthreads();
            }
            float mx = red[0];
            __syncthreads();
            red[tid] = (tid < 128) ? expf(logit - mx) : 0.f;
            __syncthreads();
            for (int o = 128; o; o >>= 1) {
                if (tid < o) red[tid] += red[tid + o];
                __syncthreads();
            }
            if (tid == 0) {
                int tgt = E[b * LE + t + 1];
                nll[t * BB + b] = (tgt != 0) ? (mx + logf(red[0]) - lg_sm[tgt]) : 0.f;
            }
        }
        gridbar();
    }

    // ================= final loss reduction (block 0) =================
    if (blk == 0) {
        float s = 0.f, cnt = 0.f;
        for (int idx = tid; idx < (LE - 1) * BB; idx += NT) {
            s += nll[idx];
            int tt = idx >> 7, b = idx & 127;
            if (E[b * LE + tt + 1] != 0) cnt += 1.f;
        }
        red[tid] = s; red2[tid] = cnt;
        __syncthreads();
        for (int o = 128; o; o >>= 1) {
            if (tid < o) { red[tid] += red[tid + o]; red2[tid] += red2[tid + o]; }
            __syncthreads();
        }
        if (tid == 0) out[0] = red[0] / fmaxf(red2[0], 1.f);
    }
}

// =====================================================================
extern "C" void kernel_launch(void* const* d_in, const int* in_sizes, int n_in,
                              void* d_out, int out_size) {
    const float* C       = (const float*)d_in[0];
    const int*   C_pad   = (const int*)d_in[1];
    const int*   E       = (const int*)d_in[2];
    const float* E_emb   = (const float*)d_in[3];
    const float* enc_Wih = (const float*)d_in[4];
    const float* enc_Whh = (const float*)d_in[5];
    const float* enc_bih = (const float*)d_in[6];
    const float* enc_bhh = (const float*)d_in[7];
    const float* dec_Wih = (const float*)d_in[8];
    const float* dec_Whh = (const float*)d_in[9];
    const float* dec_bih = (const float*)d_in[10];
    const float* dec_bhh = (const float*)d_in[11];
    const float* att_W   = (const float*)d_in[12];
    const float* out_W   = (const float*)d_in[13];
    const float* out_b   = (const float*)d_in[14];
    const float* voc_W   = (const float*)d_in[15];
    const float* voc_b   = (const float*)d_in[16];
    float* out = (float*)d_out;

    model_kernel<<<NB, NT>>>(C, C_pad, E, E_emb,
                             enc_Wih, enc_Whh, enc_bih, enc_bhh,
                             dec_Wih, dec_Whh, dec_bih, dec_bhh,
                             att_W, out_W, out_b, voc_W, voc_b, out);
}

// round 13
// speedup vs baseline: 1.0432x; 1.0432x over previous
#include <cuda_runtime.h>
#include <cstdint>
#include <cstddef>
#include <math.h>

// =====================================================================
// AutoCompleteDecoderModel as ONE persistent kernel (single graph node).
// 128 blocks x 256 threads, all co-resident (<=148 SMs) -> safe software
// grid barrier (pure spin, no nanosleep). Phases per step:
//   encoder t: [gates GEMM split-K2] bar [LSTM cell] bar
//   decoder t: [gates GEMM] bar [cell] bar [q GEMM] bar
//              [attention per-row, online softmax, 2-way unroll] bar
//              [Vnew GEMM] bar [combine+tanh+logits+CE per-row] bar
// Final loss reduction by block 0.
// B=128, Lc=Le=512, H=512, V=128.
// =====================================================================

#define BB 128
#define HH 512
#define VV 128
#define LC 512
#define LE 512
#define NB 128
#define NT 256

struct Seg { const float* A; long lda; const float* W; long ldw; int K; };

// ---------------- device scratch (allocation-free rule) ----------------
__device__ float g_h[BB * HH];
__device__ float g_c[BB * HH];
__device__ float g_Vp[BB * HH];
__device__ float g_attn[BB * HH];
__device__ float g_gates[2 * (size_t)BB * 2048];
__device__ float g_qp[8 * (size_t)BB * HH];
__device__ float g_vpart[8 * (size_t)BB * HH];
__device__ float g_hs[(size_t)BB * LC * HH];     // encoder hiddens, 134MB
__device__ float g_nll[(LE - 1) * BB];
__device__ unsigned g_count;                     // grid barrier state
__device__ volatile unsigned g_gen;

__device__ __forceinline__ float sigf(float x) { return 1.f / (1.f + expf(-x)); }

// ---------------- software grid barrier (all NB blocks resident) --------
// Arrive: one L2 atomic per block. Wait: PURE SPIN on volatile L2 load
// (dependent-load poll ~234cyc; no nanosleep quantization). Release: last
// block bumps generation after threadfence.
__device__ __forceinline__ void gridbar() {
    __syncthreads();
    if (threadIdx.x == 0) {
        __threadfence();
        unsigned g = g_gen;
        if (atomicAdd(&g_count, 1u) == NB - 1) {
            g_count = 0u;
            __threadfence();
            g_gen = g + 1u;
        } else {
            while (g_gen == g) { }
        }
        __threadfence();
    }
    __syncthreads();
}

// ---------------- one GEMM tile job: out = A @ W^T over [kstart,kend) ----
// 64x64 tile at (rowBase, colBase), K segments s0|s1|s2, 16-wide k steps.
// Segment boundaries must be multiples of 16.
__device__ __forceinline__ void gemm_job(
    float (*As)[68], float (*Bs)[68],
    const Seg& s0, const Seg& s1, const Seg& s2,
    int N, int rowBase, int colBase, int kstart, int kend,
    float* __restrict__ out)
{
    const int tid = threadIdx.x;
    const int tx = tid & 15, ty = tid >> 4;
    const int lm = tid >> 2;          // 0..63: row within tile for loads
    const int lkq = (tid & 3) * 4;    // k quad within 16

    float acc[4][4];
#pragma unroll
    for (int i = 0; i < 4; i++)
#pragma unroll
        for (int j = 0; j < 4; j++) acc[i][j] = 0.f;

    for (int kg = kstart; kg < kend; kg += 16) {
        const float *A, *W; long lda, ldw; int lk = kg;
        if (lk < s0.K)      { A = s0.A; W = s0.W; lda = s0.lda; ldw = s0.ldw; }
        else {
            lk -= s0.K;
            if (lk < s1.K)  { A = s1.A; W = s1.W; lda = s1.lda; ldw = s1.ldw; }
            else { lk -= s1.K; A = s2.A; W = s2.W; lda = s2.lda; ldw = s2.ldw; }
        }
        float4 va = *reinterpret_cast<const float4*>(A + (size_t)(rowBase + lm) * lda + lk + lkq);
        float4 vb = *reinterpret_cast<const float4*>(W + (size_t)(colBase + lm) * ldw + lk + lkq);
        As[lkq + 0][lm] = va.x; As[lkq + 1][lm] = va.y;
        As[lkq + 2][lm] = va.z; As[lkq + 3][lm] = va.w;
        Bs[lkq + 0][lm] = vb.x; Bs[lkq + 1][lm] = vb.y;
        Bs[lkq + 2][lm] = vb.z; Bs[lkq + 3][lm] = vb.w;
        __syncthreads();
#pragma unroll
        for (int k = 0; k < 16; k++) {
            float4 a4 = *reinterpret_cast<const float4*>(&As[k][ty * 4]);
            float4 b4 = *reinterpret_cast<const float4*>(&Bs[k][tx * 4]);
            float av[4] = {a4.x, a4.y, a4.z, a4.w};
            float bv[4] = {b4.x, b4.y, b4.z, b4.w};
#pragma unroll
            for (int i = 0; i < 4; i++)
#pragma unroll
                for (int j = 0; j < 4; j++) acc[i][j] += av[i] * bv[j];
        }
        __syncthreads();
    }
#pragma unroll
    for (int i = 0; i < 4; i++) {
        float4 v = make_float4(acc[i][0], acc[i][1], acc[i][2], acc[i][3]);
        *reinterpret_cast<float4*>(out + (size_t)(rowBase + ty * 4 + i) * N + colBase + tx * 4) = v;
    }
}

// =====================================================================
__global__ __launch_bounds__(NT) void model_kernel(
    const float* __restrict__ C, const int* __restrict__ C_pad,
    const int* __restrict__ E, const float* __restrict__ E_emb,
    const float* __restrict__ enc_Wih, const float* __restrict__ enc_Whh,
    const float* __restrict__ enc_bih, const float* __restrict__ enc_bhh,
    const float* __restrict__ dec_Wih, const float* __restrict__ dec_Whh,
    const float* __restrict__ dec_bih, const float* __restrict__ dec_bhh,
    const float* __restrict__ att_W, const float* __restrict__ out_W,
    const float* __restrict__ out_b, const float* __restrict__ voc_W,
    const float* __restrict__ voc_b, float* __restrict__ out)
{
    __shared__ __align__(16) float As[16][68];
    __shared__ __align__(16) float Bs[16][68];
    __shared__ __align__(16) float qs[HH];
    __shared__ __align__(16) float wacc[8][HH];
    __shared__ float wm[8], ws[8];
    __shared__ __align__(16) float tv_sm[HH];
    __shared__ float lg_sm[128];
    __shared__ float red[NT];
    __shared__ float red2[NT];
    __shared__ unsigned pmask_sm[16];            // pad bitmask for row blk (step-invariant)

    const int blk = blockIdx.x, tid = threadIdx.x;
    float* h = g_h; float* c = g_c; float* Vp = g_Vp;
    float* attn = g_attn; float* gates = g_gates;
    float* qp = g_qp; float* vpart = g_vpart;
    float* hs = g_hs; float* nll = g_nll;

    const Seg zseg{nullptr, 0, nullptr, 0, 0};

    // ---- zero init recurrent state (every replay) ----
    for (int i = blk * NT + tid; i < BB * HH; i += NB * NT) {
        h[i] = 0.f; c[i] = 0.f; Vp[i] = 0.f;
    }
    gridbar();

    // gates GEMM job decode (N=2048): 2 row tiles x 32 col tiles x 2 K-splits
    const int gcol = (blk & 31) * 64;
    const int grow = ((blk >> 5) & 1) * 64;
    const int gz   = blk >> 6;
    // small GEMM job decode (N=512): 2 row tiles x 8 col tiles x 8 K-splits
    const int scol = (blk & 7) * 64;
    const int srow = ((blk >> 3) & 1) * 64;
    const int sz   = blk >> 4;

    // ================= encoder: 512 steps =================
    for (int t = 0; t < LC; t++) {
        Seg s0{C + (size_t)t * VV, (long)LC * VV, enc_Wih, VV, VV};   // x_t @ Wih^T
        Seg s1{h, HH, enc_Whh, HH, HH};                               // h @ Whh^T
        gemm_job(As, Bs, s0, s1, zseg, 2048, grow, gcol,
                 gz * 320, gz * 320 + 320, gates + (size_t)gz * BB * 2048);
        gridbar();
        for (int idx = blk * NT + tid; idx < BB * HH; idx += NB * NT) {
            int b = idx >> 9, j = idx & 511;
            float gi = enc_bih[j] + enc_bhh[j];
            float gf = enc_bih[512 + j] + enc_bhh[512 + j];
            float gg = enc_bih[1024 + j] + enc_bhh[1024 + j];
            float go = enc_bih[1536 + j] + enc_bhh[1536 + j];
#pragma unroll
            for (int z = 0; z < 2; z++) {
                const float* g = gates + (size_t)z * BB * 2048 + (size_t)b * 2048;
                gi += g[j]; gf += g[512 + j]; gg += g[1024 + j]; go += g[1536 + j];
            }
            float cn = sigf(gf) * c[idx] + sigf(gi) * tanhf(gg);
            float hn = sigf(go) * tanhf(cn);
            c[idx] = cn;
            h[idx] = hn;
            hs[(size_t)b * (LC * HH) + (size_t)t * HH + j] = hn;
        }
        gridbar();
    }

    // ---- build pad bitmask for this block's attention row (once) ----
    if (tid < 16) {
        const int* pb = C_pad + blk * LC;
        unsigned mval = 0u;
        for (int k = 0; k < 32; k++)
            if (pb[tid * 32 + k]) mval |= (1u << k);
        pmask_sm[tid] = mval;
    }
    __syncthreads();

    // ================= decoder: 511 steps =================
    for (int t = 0; t < LE - 1; t++) {
        // ---- gates GEMM: [e_t | Vprev] @ Wih^T + h @ Whh^T, K=1152, split2
        Seg s0{E_emb + (size_t)t * VV, (long)LE * VV, dec_Wih, (long)(VV + HH), VV};
        Seg s1{Vp, HH, dec_Wih + VV, (long)(VV + HH), HH};
        Seg s2{h, HH, dec_Whh, HH, HH};
        gemm_job(As, Bs, s0, s1, s2, 2048, grow, gcol,
                 gz * 576, gz * 576 + 576, gates + (size_t)gz * BB * 2048);
        gridbar();

        // ---- LSTM cell
        for (int idx = blk * NT + tid; idx < BB * HH; idx += NB * NT) {
            int b = idx >> 9, j = idx & 511;
            float gi = dec_bih[j] + dec_bhh[j];
            float gf = dec_bih[512 + j] + dec_bhh[512 + j];
            float gg = dec_bih[1024 + j] + dec_bhh[1024 + j];
            float go = dec_bih[1536 + j] + dec_bhh[1536 + j];
#pragma unroll
            for (int z = 0; z < 2; z++) {
                const float* g = gates + (size_t)z * BB * 2048 + (size_t)b * 2048;
                gi += g[j]; gf += g[512 + j]; gg += g[1024 + j]; go += g[1536 + j];
            }
            float cn = sigf(gf) * c[idx] + sigf(gi) * tanhf(gg);
            float hn = sigf(go) * tanhf(cn);
            c[idx] = cn;
            h[idx] = hn;
        }
        gridbar();

        // ---- q = h @ attW^T (N=512, K=512, split8)
        {
            Seg sq{h, HH, att_W, HH, HH};
            gemm_job(As, Bs, sq, zseg, zseg, HH, srow, scol,
                     sz * 64, sz * 64 + 64, qp + (size_t)sz * BB * HH);
        }
        gridbar();

        // ---- attention for row b = blk: single pass, online softmax,
        //      2-way unroll over l (same per-warp FP order as before)
        {
            const int b = blk;
            for (int jj = tid; jj < HH; jj += NT) {
                float qv = 0.f;
#pragma unroll
                for (int z = 0; z < 8; z++) qv += qp[(size_t)z * (BB * HH) + b * HH + jj];
                qs[jj] = qv;
            }
            __syncthreads();

            const int warp = tid >> 5, lane = tid & 31;
            float4 qreg[4];
#pragma unroll
            for (int cch = 0; cch < 4; cch++)
                qreg[cch] = *reinterpret_cast<const float4*>(&qs[cch * 128 + lane * 4]);

            const float* eb = hs + (size_t)b * (LC * HH);

            float m = -INFINITY, s = 0.f;
            float4 a4[4];
#pragma unroll
            for (int cch = 0; cch < 4; cch++) a4[cch] = make_float4(0.f, 0.f, 0.f, 0.f);

            for (int l = warp; l < LC; l += 16) {
                const int l1 = l + 8;
                const bool v0 = ((pmask_sm[l  >> 5] >> (l  & 31)) & 1u) == 0u;
                const bool v1 = ((pmask_sm[l1 >> 5] >> (l1 & 31)) & 1u) == 0u;

                float4 e0[4], e1[4];
                float p0 = 0.f, p1 = 0.f;
                if (v0) {
                    const float4* e4 = reinterpret_cast<const float4*>(eb + (size_t)l * HH);
#pragma unroll
                    for (int cch = 0; cch < 4; cch++) e0[cch] = e4[cch * 32 + lane];
                }
                if (v1) {
                    const float4* e4 = reinterpret_cast<const float4*>(eb + (size_t)l1 * HH);
#pragma unroll
                    for (int cch = 0; cch < 4; cch++) e1[cch] = e4[cch * 32 + lane];
                }
                if (v0) {
#pragma unroll
                    for (int cch = 0; cch < 4; cch++)
                        p0 += e0[cch].x * qreg[cch].x + e0[cch].y * qreg[cch].y +
                              e0[cch].z * qreg[cch].z + e0[cch].w * qreg[cch].w;
                }
                if (v1) {
#pragma unroll
                    for (int cch = 0; cch < 4; cch++)
                        p1 += e1[cch].x * qreg[cch].x + e1[cch].y * qreg[cch].y +
                              e1[cch].z * qreg[cch].z + e1[cch].w * qreg[cch].w;
                }
                // two independent warp reductions, latency-overlapped
#pragma unroll
                for (int off = 16; off; off >>= 1) {
                    p0 += __shfl_xor_sync(0xffffffffu, p0, off);
                    p1 += __shfl_xor_sync(0xffffffffu, p1, off);
                }
                if (v0) {
                    float mn = fmaxf(m, p0);
                    float sc = __expf(m - mn);
                    float wl = __expf(p0 - mn);
                    s = s * sc + wl;
#pragma unroll
                    for (int cch = 0; cch < 4; cch++) {
                        a4[cch].x = a4[cch].x * sc + wl * e0[cch].x;
                        a4[cch].y = a4[cch].y * sc + wl * e0[cch].y;
                        a4[cch].z = a4[cch].z * sc + wl * e0[cch].z;
                        a4[cch].w = a4[cch].w * sc + wl * e0[cch].w;
                    }
                    m = mn;
                }
                if (v1) {
                    float mn = fmaxf(m, p1);
                    float sc = __expf(m - mn);
                    float wl = __expf(p1 - mn);
                    s = s * sc + wl;
#pragma unroll
                    for (int cch = 0; cch < 4; cch++) {
                        a4[cch].x = a4[cch].x * sc + wl * e1[cch].x;
                        a4[cch].y = a4[cch].y * sc + wl * e1[cch].y;
                        a4[cch].z = a4[cch].z * sc + wl * e1[cch].z;
                        a4[cch].w = a4[cch].w * sc + wl * e1[cch].w;
                    }
                    m = mn;
                }
            }
            if (lane == 0) { wm[warp] = m; ws[warp] = s; }
#pragma unroll
            for (int cch = 0; cch < 4; cch++)
                *reinterpret_cast<float4*>(&wacc[warp][cch * 128 + lane * 4]) = a4[cch];
            __syncthreads();

            float M = -INFINITY;
#pragma unroll
            for (int w = 0; w < 8; w++) M = fmaxf(M, wm[w]);
            float S = 0.f, scw[8];
#pragma unroll
            for (int w = 0; w < 8; w++) {
                scw[w] = (ws[w] > 0.f) ? __expf(wm[w] - M) : 0.f;
                S += ws[w] * scw[w];
            }
            for (int hidx = tid; hidx < HH; hidx += NT) {
                float a = 0.f;
#pragma unroll
                for (int w = 0; w < 8; w++) a += scw[w] * wacc[w][hidx];
                attn[b * HH + hidx] = a / S;
            }
        }
        gridbar();

        // ---- Vnew = [h | attn] @ outW^T (N=512, K=1024, split8)
        {
            Seg sv0{h, HH, out_W, (long)(2 * HH), HH};
            Seg sv1{attn, HH, out_W + HH, (long)(2 * HH), HH};
            gemm_job(As, Bs, sv0, sv1, zseg, HH, srow, scol,
                     sz * 128, sz * 128 + 128, vpart + (size_t)sz * BB * HH);
        }
        gridbar();

        // ---- combine + bias + tanh + logits + CE for row b = blk
        {
            const int b = blk;
            for (int j = tid; j < HH; j += NT) {
                float v = out_b[j];
#pragma unroll
                for (int z = 0; z < 8; z++) v += vpart[(size_t)z * (BB * HH) + b * HH + j];
                Vp[b * HH + j] = v;                 // raw Vnew feeds next step
                tv_sm[j] = tanhf(v);
            }
            __syncthreads();

            float logit = 0.f;
            if (tid < 128) {
                const float4* w4 = reinterpret_cast<const float4*>(voc_W + (size_t)tid * HH);
                float a = 0.f;
#pragma unroll 4
                for (int k = 0; k < 128; k++) {
                    float4 w = w4[k];
                    a += w.x * tv_sm[4 * k] + w.y * tv_sm[4 * k + 1] +
                         w.z * tv_sm[4 * k + 2] + w.w * tv_sm[4 * k + 3];
                }
                logit = a + voc_b[tid];
                lg_sm[tid] = logit;
            }
            red[tid] = (tid < 128) ? logit : -INFINITY;
            __syncthreads();
            for (int o = 128; o; o >>= 1) {
                if (tid < o) red[tid] = fmaxf(red[tid], red[tid + o]);
                __syncthreads();
            }
            float mx = red[0];
            __syncthreads();
            red[tid] = (tid < 128) ? expf(logit - mx) : 0.f;
            __syncthreads();
            for (int o = 128; o; o >>= 1) {
                if (tid < o) red[tid] += red[tid + o];
                __syncthreads();
            }
            if (tid == 0) {
                int tgt = E[b * LE + t + 1];
                nll[t * BB + b] = (tgt != 0) ? (mx + logf(red[0]) - lg_sm[tgt]) : 0.f;
            }
        }
        gridbar();
    }

    // ================= final loss reduction (block 0) =================
    if (blk == 0) {
        float s = 0.f, cnt = 0.f;
        for (int idx = tid; idx < (LE - 1) * BB; idx += NT) {
            s += nll[idx];
            int tt = idx >> 7, b = idx & 127;
            if (E[b * LE + tt + 1] != 0) cnt += 1.f;
        }
        red[tid] = s; red2[tid] = cnt;
        __syncthreads();
        for (int o = 128; o; o >>= 1) {
            if (tid < o) { red[tid] += red[tid + o]; red2[tid] += red2[tid + o]; }
            __syncthreads();
        }
        if (tid == 0) out[0] = red[0] / fmaxf(red2[0], 1.f);
    }
}

// =====================================================================
extern "C" void kernel_launch(void* const* d_in, const int* in_sizes, int n_in,
                              void* d_out, int out_size) {
    const float* C       = (const float*)d_in[0];
    const int*   C_pad   = (const int*)d_in[1];
    const int*   E       = (const int*)d_in[2];
    const float* E_emb   = (const float*)d_in[3];
    const float* enc_Wih = (const float*)d_in[4];
    const float* enc_Whh = (const float*)d_in[5];
    const float* enc_bih = (const float*)d_in[6];
    const float* enc_bhh = (const float*)d_in[7];
    const float* dec_Wih = (const float*)d_in[8];
    const float* dec_Whh = (const float*)d_in[9];
    const float* dec_bih = (const float*)d_in[10];
    const float* dec_bhh = (const float*)d_in[11];
    const float* att_W   = (const float*)d_in[12];
    const float* out_W   = (const float*)d_in[13];
    const float* out_b   = (const float*)d_in[14];
    const float* voc_W   = (const float*)d_in[15];
    const float* voc_b   = (const float*)d_in[16];
    float* out = (float*)d_out;

    model_kernel<<<NB, NT>>>(C, C_pad, E, E_emb,
                             enc_Wih, enc_Whh, enc_bih, enc_bhh,
                             dec_Wih, dec_Whh, dec_bih, dec_bhh,
                             att_W, out_W, out_b, voc_W, voc_b, out);
}